// round 11
// baseline (speedup 1.0000x reference)
#include <cuda_runtime.h>

#define Tt 64
#define Ll 64
#define Bb 128
#define Hh 64
#define NSM 148
#define NCTA (2 * NSM)
#define NTHR 256
#define NSPLIT 4
#define NTICK (Tt * Ll * NSPLIT)

#define XS_STRIDE 132
#define WS_STRIDE 68
#define SMEM_BYTES (128 * XS_STRIDE * 4 + 128 * WS_STRIDE * 4)

// Full h history h[t][l][b][u] -- no WAR hazards.
__device__ float g_h[(size_t)Tt * Ll * Bb * Hh];
// c[l][b][u] single-buffered, L2-only access.
__device__ float g_c[(size_t)Ll * Bb * Hh];
__device__ int   g_flags[Tt * Ll];
__device__ int   g_ticket;
__device__ float g_partial[Tt];

typedef unsigned long long u64;

__device__ __forceinline__ u64 pack2(float a, float b) {
    u64 r; asm("mov.b64 %0, {%1, %2};" : "=l"(r) : "f"(a), "f"(b)); return r;
}
__device__ __forceinline__ void unpack2(u64 v, float& a, float& b) {
    asm("mov.b64 {%0, %1}, %2;" : "=f"(a), "=f"(b) : "l"(v));
}
__device__ __forceinline__ void fma2(u64& acc, u64 a, u64 b) {
    asm("fma.rn.f32x2 %0, %1, %2, %0;" : "+l"(acc) : "l"(a), "l"(b));
}
__device__ __forceinline__ float sigm(float x) {
    return __fdividef(1.0f, 1.0f + __expf(-x));
}
// tanh(x) = 1 - 2/(exp(2x)+1); saturates correctly at +/-inf of __expf.
__device__ __forceinline__ float tanh_fast(float x) {
    return 1.0f - 2.0f * __fdividef(1.0f, __expf(2.0f * x) + 1.0f);
}
__device__ __forceinline__ int ldacq(const int* p) {
    int v; asm volatile("ld.acquire.gpu.global.b32 %0, [%1];" : "=r"(v) : "l"(p)); return v;
}
__device__ __forceinline__ void poll4(const int* p) {
    while (ldacq(p) < NSPLIT) { }
}
__device__ __forceinline__ void rel_add(int* p) {
    asm volatile("red.release.gpu.global.add.s32 [%0], 1;" :: "l"(p) : "memory");
}

__global__ void init_kernel() {
    int i = blockIdx.x * blockDim.x + threadIdx.x;
    if (i < Tt * Ll) g_flags[i] = 0;
    if (i == 0) g_ticket = 0;
}

// 64-k FMA sweep: k in [k0, k0+64), acc += Xs[row][k] * Ws[k][col]
__device__ __forceinline__ void gemm64(const float* __restrict__ Xs,
                                       const float* __restrict__ Ws,
                                       int r0, int u0, int k0, u64 acc[4][4]) {
    #pragma unroll 2
    for (int k4 = k0; k4 < k0 + 64; k4 += 4) {
        float4 av[4];
        #pragma unroll
        for (int i = 0; i < 4; i++)
            av[i] = *(const float4*)&Xs[(r0 + i) * XS_STRIDE + k4];
        #pragma unroll
        for (int q = 0; q < 4; q++) {
            u64 b2[4];
            const float* wr = Ws + (k4 + q) * WS_STRIDE + u0;
            #pragma unroll
            for (int g = 0; g < 4; g++) b2[g] = *(const u64*)(wr + g * 16);
            #pragma unroll
            for (int i = 0; i < 4; i++) {
                float a = ((const float*)&av[i])[q];
                u64 a2 = pack2(a, a);
                #pragma unroll
                for (int g = 0; g < 4; g++) fma2(acc[i][g], a2, b2[g]);
            }
        }
    }
}

// Persistent wavefront kernel, 4 CTAs per cell (64 output cols each),
// 2 CTAs resident per SM so spins overlap with the co-CTA's FMA work.
// Dynamic diag-major ticketing (atomic counter): deadlock-free at any
// residency -- every grabbed ticket's deps are strictly earlier grabs.
// Adaptive split: the two 64-k GEMM halves (h_in <- l-flag, h_prev <- t-flag)
// run in flag-arrival order; separate accumulators keep summation order
// fixed => bit-deterministic output.
__global__ void __launch_bounds__(NTHR, 2) wave_kernel(
    const float* __restrict__ x,  const float* __restrict__ W0,
    const float* __restrict__ b0, const float* __restrict__ Wl,
    const float* __restrict__ bl)
{
    extern __shared__ float smem[];
    float* Xs = smem;                       // [128][XS_STRIDE] cols 0-63 h_in, 64-127 h_prev
    float* Ws = smem + 128 * XS_STRIDE;     // [128][WS_STRIDE] col j = g*16+u
    __shared__ int sp[4];                   // {t, l, cg, mode}; mode<0 => exit

    const int tid = threadIdx.x;
    const int r0  = (tid >> 3) * 4;
    const int u0  = (tid & 7) * 2;
    const int srow = tid >> 1;
    const int shalf = tid & 1;

    int s_cur = 0, base = 0;   // incremental diag decode (w is monotone per CTA)

    for (;;) {
        if (tid == 0) {
            int w = atomicAdd(&g_ticket, 1);
            if (w >= NTICK) sp[3] = -1;
            else {
                for (;;) {
                    int nd4 = min(min(s_cur + 1, 127 - s_cur), 64) * NSPLIT;
                    if (w < base + nd4) break;
                    base += nd4; s_cur++;
                }
                int rem = w - base;
                int cg = rem & 3, cell = rem >> 2;
                int t = ((s_cur > 63) ? (s_cur - 63) : 0) + cell;
                sp[0] = t; sp[1] = s_cur - t; sp[2] = cg; sp[3] = 0;
            }
        }
        __syncthreads();
        if (sp[3] < 0) break;
        const int t = sp[0], l = sp[1], cg = sp[2];
        __syncthreads();   // sp consumed; also prev-iter smem reusable

        // ---- stage W tile (no deps; overlaps the spins below) ----
        if (l > 0) {
            const float* wrow = Wl + (size_t)(l - 1) * 128 * 256 + (size_t)srow * 256;
            float* dst = Ws + srow * WS_STRIDE + shalf * 32;
            #pragma unroll
            for (int e = 0; e < 2; e++) {
                const float4* s4 = (const float4*)(wrow + (shalf * 2 + e) * 64 + cg * 16);
                float4* d4 = (float4*)(dst + e * 16);
                #pragma unroll
                for (int q = 0; q < 4; q++) d4[q] = s4[q];
            }
        } else if (srow < 68) {
            float* dst = Ws + srow * WS_STRIDE + shalf * 32;
            if (srow < 65) {
                const float* wrow = W0 + (size_t)srow * 256;
                #pragma unroll
                for (int e = 0; e < 2; e++) {
                    const float4* s4 = (const float4*)(wrow + (shalf * 2 + e) * 64 + cg * 16);
                    float4* d4 = (float4*)(dst + e * 16);
                    #pragma unroll
                    for (int q = 0; q < 4; q++) d4[q] = s4[q];
                }
            } else {
                float4 z = make_float4(0.f, 0.f, 0.f, 0.f);
                float4* d4 = (float4*)dst;
                #pragma unroll
                for (int q = 0; q < 8; q++) d4[q] = z;
            }
        }

        float2 bpre[4];
        {
            const float* bias = (l == 0) ? b0 : (bl + (l - 1) * 256);
            #pragma unroll
            for (int g = 0; g < 4; g++)
                bpre[g] = *(const float2*)(bias + g * 64 + cg * 16 + u0);
        }

        // accI seeded with bias; accP zero.  z = (bias + zI) + zP (fixed order).
        u64 accI[4][4], accP[4][4];
        #pragma unroll
        for (int g = 0; g < 4; g++) {
            u64 bs = pack2(bpre[g].x, bpre[g].y);
            #pragma unroll
            for (int i = 0; i < 4; i++) { accI[i][g] = bs; accP[i][g] = 0ULL; }
        }

        const float* hin_base   = (l > 0) ? &g_h[((size_t)t * Ll + (l - 1)) * Bb * Hh] : (const float*)0;
        const float* hprev_base = (t > 0) ? &g_h[((size_t)(t - 1) * Ll + l) * Bb * Hh] : (const float*)0;

        if (l == 0) {
            // ---- GEMM over [x | h_prev | 0pad], 68 k ----
            if (tid == 0 && t > 0) poll4(&g_flags[(t - 1) * Ll + l]);
            __syncthreads();
            {
                float* dst = Xs + srow * XS_STRIDE;
                int c0 = shalf * 34;
                #pragma unroll 2
                for (int c = c0; c < c0 + 34; c++) {
                    float v = 0.f;
                    if (c == 0) v = x[srow * Tt + t];
                    else if (c < 65 && t > 0) v = hprev_base[srow * Hh + (c - 1)];
                    dst[c] = v;
                }
            }
            __syncthreads();
            gemm64(Xs, Ws, r0, u0, 0, accI);
            {
                float4 av[4];
                #pragma unroll
                for (int i = 0; i < 4; i++)
                    av[i] = *(const float4*)&Xs[(r0 + i) * XS_STRIDE + 64];
                #pragma unroll
                for (int q = 0; q < 4; q++) {
                    u64 b2[4];
                    const float* wr = Ws + (64 + q) * WS_STRIDE + u0;
                    #pragma unroll
                    for (int g = 0; g < 4; g++) b2[g] = *(const u64*)(wr + g * 16);
                    #pragma unroll
                    for (int i = 0; i < 4; i++) {
                        float a = ((const float*)&av[i])[q];
                        u64 a2 = pack2(a, a);
                        #pragma unroll
                        for (int g = 0; g < 4; g++) fma2(accI[i][g], a2, b2[g]);
                    }
                }
            }
        } else if (t == 0) {
            // ---- only h_in half ----
            if (tid == 0) poll4(&g_flags[t * Ll + (l - 1)]);
            __syncthreads();
            {
                const float4* s = (const float4*)(hin_base + srow * Hh + shalf * 32);
                float4* dt = (float4*)(Xs + srow * XS_STRIDE + shalf * 32);
                #pragma unroll
                for (int q = 0; q < 8; q++) dt[q] = s[q];
            }
            __syncthreads();
            gemm64(Xs, Ws, r0, u0, 0, accI);
        } else {
            // ---- adaptive dual-half path ----
            const int* fI = &g_flags[t * Ll + (l - 1)];
            const int* fP = &g_flags[(t - 1) * Ll + l];
            if (tid == 0) {
                int a, b;
                for (;;) {
                    a = ldacq(fI); b = ldacq(fP);
                    if (a >= NSPLIT || b >= NSPLIT) break;
                }
                sp[3] = (a >= NSPLIT) ? ((b >= NSPLIT) ? 2 : 0) : 1;
            }
            __syncthreads();
            const int first = sp[3];

            if (first == 2) {
                // both ready: fused full-128k path
                {
                    const float* src = (shalf == 0) ? (hin_base + srow * Hh)
                                                    : (hprev_base + srow * Hh);
                    float* dt = Xs + srow * XS_STRIDE + shalf * 64;
                    #pragma unroll
                    for (int q = 0; q < 16; q++)
                        ((float4*)dt)[q] = ((const float4*)src)[q];
                }
                __syncthreads();
                gemm64(Xs, Ws, r0, u0, 0, accI);
                gemm64(Xs, Ws, r0, u0, 64, accP);
            } else if (first == 0) {
                // h_in first
                {
                    const float4* s = (const float4*)(hin_base + srow * Hh + shalf * 32);
                    float4* dt = (float4*)(Xs + srow * XS_STRIDE + shalf * 32);
                    #pragma unroll
                    for (int q = 0; q < 8; q++) dt[q] = s[q];
                }
                __syncthreads();
                gemm64(Xs, Ws, r0, u0, 0, accI);
                if (tid == 0) poll4(fP);
                __syncthreads();
                {
                    const float4* s = (const float4*)(hprev_base + srow * Hh + shalf * 32);
                    float4* dt = (float4*)(Xs + srow * XS_STRIDE + 64 + shalf * 32);
                    #pragma unroll
                    for (int q = 0; q < 8; q++) dt[q] = s[q];
                }
                __syncthreads();
                gemm64(Xs, Ws, r0, u0, 64, accP);
            } else {
                // h_prev first
                {
                    const float4* s = (const float4*)(hprev_base + srow * Hh + shalf * 32);
                    float4* dt = (float4*)(Xs + srow * XS_STRIDE + 64 + shalf * 32);
                    #pragma unroll
                    for (int q = 0; q < 8; q++) dt[q] = s[q];
                }
                __syncthreads();
                gemm64(Xs, Ws, r0, u0, 64, accP);
                if (tid == 0) poll4(fI);
                __syncthreads();
                {
                    const float4* s = (const float4*)(hin_base + srow * Hh + shalf * 32);
                    float4* dt = (float4*)(Xs + srow * XS_STRIDE + shalf * 32);
                    #pragma unroll
                    for (int q = 0; q < 8; q++) dt[q] = s[q];
                }
                __syncthreads();
                gemm64(Xs, Ws, r0, u0, 0, accI);
            }
        }

        // ---- gates epilogue: z = accI + accP (fixed order) ----
        float* cptr = &g_c[(size_t)l * Bb * Hh];
        float* hout = &g_h[((size_t)t * Ll + l) * Bb * Hh];
        #pragma unroll
        for (int i = 0; i < 4; i++) {
            int row = r0 + i;
            int off = row * Hh + cg * 16 + u0;
            float z0[4], z1[4];
            #pragma unroll
            for (int g = 0; g < 4; g++) {
                float iA, iB, pA, pB;
                unpack2(accI[i][g], iA, iB);
                unpack2(accP[i][g], pA, pB);
                z0[g] = iA + pA; z1[g] = iB + pB;
            }
            float cp0 = 0.f, cp1 = 0.f;
            if (t > 0) {
                float2 cp = __ldcg((const float2*)(cptr + off));
                cp0 = cp.x; cp1 = cp.y;
            }
            float c20 = cp0 * sigm(z0[2]) + sigm(z0[0]) * tanh_fast(z0[1]);
            float c21 = cp1 * sigm(z1[2]) + sigm(z1[0]) * tanh_fast(z1[1]);
            float h20 = tanh_fast(c20) * sigm(z0[3]);
            float h21 = tanh_fast(c21) * sigm(z1[3]);
            __stcg((float2*)(cptr + off), make_float2(c20, c21));
            *(float2*)(hout + off) = make_float2(h20, h21);
        }

        __syncthreads();   // all stores issued
        if (tid == 0) rel_add(&g_flags[t * Ll + l]);
    }
}

// pred[b,t] = relu(h[t][63][b][:] . Wd[t] + bd[t]); per-t squared-error partials.
__global__ void dense_kernel(const float* __restrict__ labels, const float* __restrict__ Wd,
                             const float* __restrict__ bd, float* __restrict__ out)
{
    int t = blockIdx.x;
    int b = threadIdx.x;
    __shared__ float wd[64];
    __shared__ float red[128];
    if (b < 64) wd[b] = Wd[t * 64 + b];
    __syncthreads();
    const float* hrow = &g_h[(((size_t)t * Ll + 63) * Bb + b) * Hh];
    float acc = 0.f;
    #pragma unroll
    for (int u = 0; u < 64; u++) acc += hrow[u] * wd[u];
    float p = acc + bd[t];
    p = (p > 0.f) ? p : 0.f;
    out[b * 64 + t] = p;
    float e = labels[b * 64 + t] - p;
    red[b] = e * e;
    __syncthreads();
    for (int s = 64; s > 0; s >>= 1) {
        if (b < s) red[b] += red[b + s];
        __syncthreads();
    }
    if (b == 0) g_partial[t] = red[0];
}

__global__ void loss_kernel(float* out, int out_size)
{
    __shared__ float red[64];
    int tid = threadIdx.x;
    red[tid] = g_partial[tid];
    __syncthreads();
    for (int s = 32; s > 0; s >>= 1) {
        if (tid < s) red[tid] += red[tid + s];
        __syncthreads();
    }
    if (tid == 0 && out_size > Bb * Tt) out[Bb * Tt] = red[0] / (float)(Bb * Tt);
}

extern "C" void kernel_launch(void* const* d_in, const int* in_sizes, int n_in,
                              void* d_out, int out_size) {
    const float* x      = (const float*)d_in[0];
    const float* labels = (const float*)d_in[1];
    const float* W0     = (const float*)d_in[2];
    const float* b0     = (const float*)d_in[3];
    const float* Wl     = (const float*)d_in[4];
    const float* bl     = (const float*)d_in[5];
    const float* Wd     = (const float*)d_in[6];
    const float* bd     = (const float*)d_in[7];
    float* out = (float*)d_out;

    cudaFuncSetAttribute(wave_kernel, cudaFuncAttributeMaxDynamicSharedMemorySize, SMEM_BYTES);

    init_kernel<<<16, 256>>>();
    wave_kernel<<<NCTA, NTHR, SMEM_BYTES>>>(x, W0, b0, Wl, bl);
    dense_kernel<<<64, 128>>>(labels, Wd, bd, out);
    loss_kernel<<<1, 64>>>(out, out_size);
}